// round 10
// baseline (speedup 1.0000x reference)
#include <cuda_runtime.h>
#include <cuda_bf16.h>
#include <cstdint>

#define NN     100000
#define NEDGE  1600000
#define HID    128
#define SCAN_B 1024
#define NB1    ((NN + SCAN_B - 1) / SCAN_B)   // 98

// node-half split (h0 multiple of 256 for clean gemm tiles)
#define NH0    50176
#define NH1    (NN - NH0)    // 49824

// ---------------- scratch (static device globals; no allocation) ----------------
__device__ float  g_dinv[NN];
__device__ int    g_eidx[2 * NEDGE];
__device__ int    g_cnt[NN];
__device__ int    g_cur[NN];
__device__ int    g_rowptr[NN + 1];
__device__ int    g_bsum[NB1];
__device__ float2 g_csr[NEDGE];                 // {src (bitcast int), norm}
__device__ float  g_xw1[(size_t)NN * HID];      // h @ W buffer A (layers 1,3)
__device__ float  g_xw2[(size_t)NN * HID];      // h @ W buffer B (layer 2)
__device__ float  g_h  [(size_t)NN * HID];      // post-relu features
__device__ unsigned char g_wimg[3 * 2 * 32768]; // per-layer W_hi/W_lo plain [n][k] bf16 images
__device__ int    g_is64;

// ---------------- host-side stream/event resources ----------------
struct HxRes {
    cudaStream_t s2;
    cudaEvent_t evA, evB, evG1, evA1, evG2, evA2;
    HxRes() {
        cudaStreamCreateWithFlags(&s2, cudaStreamNonBlocking);
        cudaEventCreateWithFlags(&evA,  cudaEventDisableTiming);
        cudaEventCreateWithFlags(&evB,  cudaEventDisableTiming);
        cudaEventCreateWithFlags(&evG1, cudaEventDisableTiming);
        cudaEventCreateWithFlags(&evA1, cudaEventDisableTiming);
        cudaEventCreateWithFlags(&evG2, cudaEventDisableTiming);
        cudaEventCreateWithFlags(&evA2, cudaEventDisableTiming);
    }
};
static HxRes g_res;

// ================= helpers =================
__device__ __forceinline__ uint32_t smem_u32(const void* p) {
    uint32_t a;
    asm("{ .reg .u64 t; cvta.to.shared.u64 t, %1; cvt.u32.u64 %0, t; }" : "=r"(a) : "l"(p));
    return a;
}
__device__ __forceinline__ uint32_t bf2pack(float lo, float hi) {
    uint32_t r;
    asm("cvt.rn.bf16x2.f32 %0, %1, %2;" : "=r"(r) : "f"(hi), "f"(lo));
    return r;
}
__device__ __forceinline__ float bfhi(float a) {
    return __bfloat162float(__float2bfloat16(a));
}
__device__ __forceinline__ void ldsm_x4(uint32_t addr, uint32_t r[4]) {
    asm volatile("ldmatrix.sync.aligned.m8n8.x4.shared.b16 {%0,%1,%2,%3}, [%4];"
                 : "=r"(r[0]), "=r"(r[1]), "=r"(r[2]), "=r"(r[3]) : "r"(addr));
}
__device__ __forceinline__ void mma_bf16(float c[4], const uint32_t a[4], const uint32_t* b) {
    asm volatile(
        "mma.sync.aligned.m16n8k16.row.col.f32.bf16.bf16.f32 "
        "{%0,%1,%2,%3}, {%4,%5,%6,%7}, {%8,%9}, {%0,%1,%2,%3};"
        : "+f"(c[0]), "+f"(c[1]), "+f"(c[2]), "+f"(c[3])
        : "r"(a[0]), "r"(a[1]), "r"(a[2]), "r"(a[3]), "r"(b[0]), "r"(b[1]));
}

// ---------------- edge index width detection ----------------
__global__ void k_detect(const int* __restrict__ w) {
    int zeros = 0;
    for (int i = 0; i < 256; i++) zeros += (w[2 * i + 1] == 0) ? 1 : 0;
    g_is64 = (zeros == 256) ? 1 : 0;
}

__global__ void k_zero() {
    int i = blockIdx.x * blockDim.x + threadIdx.x;
    if (i >= NN) return;
    g_dinv[i] = 1.0f;
    g_cnt[i] = 0;
    g_cur[i] = 0;
}

// ---------------- fused: convert + weighted degree + histogram ----------------
__global__ void k_prep(const void* __restrict__ p, const float* __restrict__ ew) {
    int e = blockIdx.x * blockDim.x + threadIdx.x;
    if (e >= NEDGE) return;
    int r, c;
    if (g_is64) {
        r = (int)((const long long*)p)[e];
        c = (int)((const long long*)p)[NEDGE + e];
    } else {
        r = ((const int*)p)[e];
        c = ((const int*)p)[NEDGE + e];
    }
    g_eidx[e] = r;
    g_eidx[NEDGE + e] = c;
    atomicAdd(&g_dinv[c], ew[e]);
    atomicAdd(&g_cnt[c], 1);
}

// ---------------- scan (block-level) + dinv finalize ----------------
__global__ __launch_bounds__(SCAN_B) void k_scan1() {
    __shared__ int sh[SCAN_B];
    int t = threadIdx.x;
    int i = blockIdx.x * SCAN_B + t;
    int v = (i < NN) ? g_cnt[i] : 0;
    sh[t] = v;
    if (i < NN) {
        float d = g_dinv[i];
        g_dinv[i] = (d > 0.0f) ? rsqrtf(d) : 0.0f;
    }
    __syncthreads();
#pragma unroll
    for (int off = 1; off < SCAN_B; off <<= 1) {
        int add = (t >= off) ? sh[t - off] : 0;
        __syncthreads();
        sh[t] += add;
        __syncthreads();
    }
    if (i < NN) g_rowptr[i] = sh[t] - v;
    if (t == SCAN_B - 1) g_bsum[blockIdx.x] = sh[t];
}

__global__ void k_scan2() {
    if (threadIdx.x == 0) {
        int run = 0;
        for (int b = 0; b < NB1; b++) { int s = g_bsum[b]; g_bsum[b] = run; run += s; }
    }
}

__global__ __launch_bounds__(SCAN_B) void k_scan3() {
    int i = blockIdx.x * SCAN_B + threadIdx.x;
    if (i < NN) g_rowptr[i] += g_bsum[blockIdx.x];
    if (i == 0) g_rowptr[NN] = NEDGE;
}

__global__ void k_scatter(const float* __restrict__ ew) {
    int e = blockIdx.x * blockDim.x + threadIdx.x;
    if (e >= NEDGE) return;
    int r = g_eidx[e];
    int c = g_eidx[NEDGE + e];
    float nm = g_dinv[r] * ew[e] * g_dinv[c];
    int pos = g_rowptr[c] + atomicAdd(&g_cur[c], 1);
    g_csr[pos] = make_float2(__int_as_float(r), nm);
}

// ---------------- W -> bf16 hi/lo plain [n][k] images (B^T for row.col mma) ----------------
__global__ void k_wconv(const float* __restrict__ W, int layer) {
    int i = blockIdx.x * blockDim.x + threadIdx.x;
    if (i >= HID * HID) return;
    int n = i >> 7, k = i & 127;
    float w = W[k * HID + n];                       // B[n][k] = W[k][n]
    __nv_bfloat16 h = __float2bfloat16(w);
    float hf = __bfloat162float(h);
    __nv_bfloat16 l = __float2bfloat16(w - hf);
    unsigned char* base = g_wimg + (size_t)layer * 65536;
    *(uint16_t*)(base + (size_t)(n * HID + k) * 2)         = __bfloat16_as_ushort(h);
    *(uint16_t*)(base + 32768 + (size_t)(n * HID + k) * 2) = __bfloat16_as_ushort(l);
}

// ---------------- mma.sync split-bf16 GEMM: rows [rowOff, rowOff+256*grid) ----------------
#define TSTRIDE 272
#define SM_AHI  0
#define SM_ALO  69632
#define SM_BHI  139264
#define SM_BLO  174080
#define SM_TOT  208896

__global__ __launch_bounds__(512, 1) void k_gemm(const float* __restrict__ Ain,
                                                 int use_h, int layer,
                                                 float* __restrict__ xwOut,
                                                 int rowOff, int n) {
    extern __shared__ char smem[];
    uint32_t sbase = smem_u32(smem);
    const float* A = use_h ? g_h : Ain;
    int tid = threadIdx.x;
    int wid = tid >> 5, lane = tid & 31;
    int rowBase = rowOff + blockIdx.x * 256;
    int m_base = (wid & 3) * 64;
    int n_base = (wid >> 2) * 32;

    // --- A tile: 256 rows x 128 cols fp32 -> bf16 hi/lo padded ---
#pragma unroll
    for (int it = 0; it < 8; it++) {
        int item = tid + 512 * it;
        int row = item >> 4, c8 = (item & 15) * 8;
        int grow = rowBase + row;
        float f[8];
        if (grow < n) {
            float4 v0 = *(const float4*)(A + (size_t)grow * HID + c8);
            float4 v1 = *(const float4*)(A + (size_t)grow * HID + c8 + 4);
            f[0] = v0.x; f[1] = v0.y; f[2] = v0.z; f[3] = v0.w;
            f[4] = v1.x; f[5] = v1.y; f[6] = v1.z; f[7] = v1.w;
        } else {
#pragma unroll
            for (int j = 0; j < 8; j++) f[j] = 0.0f;
        }
        float hf[8], lf[8];
#pragma unroll
        for (int j = 0; j < 8; j++) { hf[j] = bfhi(f[j]); lf[j] = f[j] - hf[j]; }
        uint4 H = make_uint4(bf2pack(hf[0], hf[1]), bf2pack(hf[2], hf[3]),
                             bf2pack(hf[4], hf[5]), bf2pack(hf[6], hf[7]));
        uint4 L = make_uint4(bf2pack(lf[0], lf[1]), bf2pack(lf[2], lf[3]),
                             bf2pack(lf[4], lf[5]), bf2pack(lf[6], lf[7]));
        uint32_t off = (uint32_t)row * TSTRIDE + c8 * 2;
        *(uint4*)(smem + SM_AHI + off) = H;
        *(uint4*)(smem + SM_ALO + off) = L;
    }

    // --- B tiles ---
    {
        const uint4* srcH = (const uint4*)(g_wimg + (size_t)layer * 65536);
        const uint4* srcL = (const uint4*)(g_wimg + (size_t)layer * 65536 + 32768);
#pragma unroll
        for (int it = 0; it < 4; it++) {
            int item = tid + 512 * it;
            int row = item >> 4, c8 = (item & 15) * 8;
            uint32_t off = (uint32_t)row * TSTRIDE + c8 * 2;
            *(uint4*)(smem + SM_BHI + off) = srcH[item];
            *(uint4*)(smem + SM_BLO + off) = srcL[item];
        }
    }
    __syncthreads();

    float acc[4][4][4];
#pragma unroll
    for (int mt = 0; mt < 4; mt++)
#pragma unroll
        for (int nt = 0; nt < 4; nt++)
#pragma unroll
            for (int c = 0; c < 4; c++) acc[mt][nt][c] = 0.0f;

    int aRow = lane & 15;
    int aCol = (lane >> 4) * 8;
    int bRow = (lane & 7) + ((lane >> 4) << 3);
    int bCol = ((lane >> 3) & 1) * 8;

    // --- pass 1: Bh shared between Ah and Al ---
#pragma unroll
    for (int kk = 0; kk < 128; kk += 16) {
        uint32_t b[2][4];
#pragma unroll
        for (int np = 0; np < 2; np++) {
            uint32_t addr = sbase + SM_BHI + (uint32_t)(n_base + np * 16 + bRow) * TSTRIDE
                          + (kk + bCol) * 2;
            ldsm_x4(addr, b[np]);
        }
        uint32_t ah[4][4], al[4][4];
#pragma unroll
        for (int mt = 0; mt < 4; mt++) {
            uint32_t ra = (uint32_t)(m_base + mt * 16 + aRow) * TSTRIDE + (kk + aCol) * 2;
            ldsm_x4(sbase + SM_AHI + ra, ah[mt]);
            ldsm_x4(sbase + SM_ALO + ra, al[mt]);
        }
#pragma unroll
        for (int mt = 0; mt < 4; mt++)
#pragma unroll
            for (int nt = 0; nt < 4; nt++) {
                mma_bf16(acc[mt][nt], ah[mt], &b[nt >> 1][(nt & 1) * 2]);
                mma_bf16(acc[mt][nt], al[mt], &b[nt >> 1][(nt & 1) * 2]);
            }
    }

    // --- pass 2: Ah x Bl ---
#pragma unroll
    for (int kk = 0; kk < 128; kk += 16) {
        uint32_t b[2][4];
#pragma unroll
        for (int np = 0; np < 2; np++) {
            uint32_t addr = sbase + SM_BLO + (uint32_t)(n_base + np * 16 + bRow) * TSTRIDE
                          + (kk + bCol) * 2;
            ldsm_x4(addr, b[np]);
        }
        uint32_t ah[4][4];
#pragma unroll
        for (int mt = 0; mt < 4; mt++) {
            uint32_t ra = (uint32_t)(m_base + mt * 16 + aRow) * TSTRIDE + (kk + aCol) * 2;
            ldsm_x4(sbase + SM_AHI + ra, ah[mt]);
        }
#pragma unroll
        for (int mt = 0; mt < 4; mt++)
#pragma unroll
            for (int nt = 0; nt < 4; nt++)
                mma_bf16(acc[mt][nt], ah[mt], &b[nt >> 1][(nt & 1) * 2]);
    }

    // --- epilogue ---
#pragma unroll
    for (int mt = 0; mt < 4; mt++) {
        int r0 = rowBase + m_base + mt * 16 + (lane >> 2);
        int r1 = r0 + 8;
#pragma unroll
        for (int nt = 0; nt < 4; nt++) {
            int c0 = n_base + nt * 8 + (lane & 3) * 2;
            if (r0 < n)
                *(float2*)(xwOut + (size_t)r0 * HID + c0) =
                    make_float2(acc[mt][nt][0], acc[mt][nt][1]);
            if (r1 < n)
                *(float2*)(xwOut + (size_t)r1 * HID + c0) =
                    make_float2(acc[mt][nt][2], acc[mt][nt][3]);
        }
    }
}

// ---------------- pull aggregation: one warp per node, fp32 gathers ----------------
__global__ __launch_bounds__(256) void k_agg(const float* __restrict__ xwIn,
                                             const float* __restrict__ b,
                                             int nodeOff, int nodeCnt,
                                             int last,
                                             const float* __restrict__ lw,
                                             const float* __restrict__ lb,
                                             float* __restrict__ y) {
    int gt = blockIdx.x * 256 + threadIdx.x;
    int rel = gt >> 5;
    int lane = gt & 31;
    if (rel >= nodeCnt) return;
    int node = nodeOff + rel;

    int s = g_rowptr[node];
    int e = g_rowptr[node + 1];

    float4 acc = make_float4(0.f, 0.f, 0.f, 0.f);
    int i = s;
    for (; i + 3 < e; i += 4) {
        float2 c0 = g_csr[i];
        float2 c1 = g_csr[i + 1];
        float2 c2 = g_csr[i + 2];
        float2 c3 = g_csr[i + 3];
        float4 v0 = *(const float4*)(xwIn + (size_t)__float_as_int(c0.x) * HID + lane * 4);
        float4 v1 = *(const float4*)(xwIn + (size_t)__float_as_int(c1.x) * HID + lane * 4);
        float4 v2 = *(const float4*)(xwIn + (size_t)__float_as_int(c2.x) * HID + lane * 4);
        float4 v3 = *(const float4*)(xwIn + (size_t)__float_as_int(c3.x) * HID + lane * 4);
        acc.x += c0.y * v0.x + c1.y * v1.x + c2.y * v2.x + c3.y * v3.x;
        acc.y += c0.y * v0.y + c1.y * v1.y + c2.y * v2.y + c3.y * v3.y;
        acc.z += c0.y * v0.z + c1.y * v1.z + c2.y * v2.z + c3.y * v3.z;
        acc.w += c0.y * v0.w + c1.y * v1.w + c2.y * v2.w + c3.y * v3.w;
    }
    for (; i < e; i++) {
        float2 c0 = g_csr[i];
        float4 v0 = *(const float4*)(xwIn + (size_t)__float_as_int(c0.x) * HID + lane * 4);
        acc.x += c0.y * v0.x;
        acc.y += c0.y * v0.y;
        acc.z += c0.y * v0.z;
        acc.w += c0.y * v0.w;
    }

    // self loop
    float di = g_dinv[node];
    float d2 = di * di;
    float4 sv = *(const float4*)(xwIn + (size_t)node * HID + lane * 4);
    acc.x += d2 * sv.x;
    acc.y += d2 * sv.y;
    acc.z += d2 * sv.z;
    acc.w += d2 * sv.w;

    float4 bb = *(const float4*)(b + lane * 4);
    float4 h;
    h.x = fmaxf(acc.x + bb.x, 0.f);
    h.y = fmaxf(acc.y + bb.y, 0.f);
    h.z = fmaxf(acc.z + bb.z, 0.f);
    h.w = fmaxf(acc.w + bb.w, 0.f);

    if (!last) {
        *(float4*)(g_h + (size_t)node * HID + lane * 4) = h;
    } else {
        float4 w = *(const float4*)(lw + lane * 4);
        float sum = h.x * w.x + h.y * w.y + h.z * w.z + h.w * w.w;
#pragma unroll
        for (int off = 16; off > 0; off >>= 1)
            sum += __shfl_xor_sync(0xFFFFFFFFu, sum, off);
        if (lane == 0) y[node] = sum + lb[0];
    }
}

// ---------------- launch ----------------
extern "C" void kernel_launch(void* const* d_in, const int* in_sizes, int n_in,
                              void* d_out, int out_size) {
    const float* x   = (const float*)d_in[0];
    const void*  ei  = d_in[1];
    const float* ea  = (const float*)d_in[2];
    const float* W1  = (const float*)d_in[3];
    const float* b1  = (const float*)d_in[4];
    const float* W2  = (const float*)d_in[5];
    const float* b2  = (const float*)d_in[6];
    const float* W3  = (const float*)d_in[7];
    const float* b3  = (const float*)d_in[8];
    const float* lw  = (const float*)d_in[9];
    const float* lb  = (const float*)d_in[10];
    float* y = (float*)d_out;

    (void)in_sizes; (void)n_in; (void)out_size;

    static int s_attr_done = 0;
    if (!s_attr_done) {
        cudaFuncSetAttribute(k_gemm, cudaFuncAttributeMaxDynamicSharedMemorySize, SM_TOT);
        s_attr_done = 1;
    }

    // device-symbol addresses for xw buffers
    static float* s_xw1 = nullptr;
    static float* s_xw2 = nullptr;
    if (!s_xw1) {
        cudaGetSymbolAddress((void**)&s_xw1, g_xw1);
        cudaGetSymbolAddress((void**)&s_xw2, g_xw2);
    }

    const int GEMM_FULL = (NN + 255) / 256;       // 391
    const int GEMM_H0   = NH0 / 256;              // 196
    const int GEMM_H1   = (NH1 + 255) / 256;      // 195
    const int EW_BLOCKS   = (NEDGE + 255) / 256;
    const int NODE_BLOCKS = (NN + 255) / 256;
    const int AGG_H0 = (NH0 * 32 + 255) / 256;    // 6272
    const int AGG_H1 = (NH1 * 32 + 255) / 256;    // 6228
    const int AGG_FULL = (NN * 32 + 255) / 256;   // 12500

    cudaStream_t s2 = g_res.s2;

    // fork: s2 branches off the capture (default) stream
    cudaEventRecord(g_res.evA, 0);
    cudaStreamWaitEvent(s2, g_res.evA, 0);

    // default: W images + full layer-1 GEMM (k_gemm = 4th launch -> profiled)
    k_wconv<<<64, 256>>>(W1, 0);
    k_wconv<<<64, 256>>>(W2, 1);
    k_wconv<<<64, 256>>>(W3, 2);
    k_gemm<<<GEMM_FULL, 512, SM_TOT>>>(x, 0, 0, s_xw1, 0, NN);
    cudaEventRecord(g_res.evG1, 0);               // gemm1 done

    // s2: edge setup chain, concurrent with gemm1
    k_detect<<<1, 1, 0, s2>>>((const int*)ei);
    k_zero<<<NODE_BLOCKS, 256, 0, s2>>>();
    k_prep<<<EW_BLOCKS, 256, 0, s2>>>(ei, ea);
    k_scan1<<<NB1, SCAN_B, 0, s2>>>();
    k_scan2<<<1, 32, 0, s2>>>();
    k_scan3<<<NB1, SCAN_B, 0, s2>>>();
    k_scatter<<<EW_BLOCKS, 256, 0, s2>>>(ea);
    cudaEventRecord(g_res.evB, s2);               // setup done

    // ---- layer 1 agg / layer 2 gemm, pipelined by node halves ----
    // s2: agg1(h1) after setup (in-order) + gemm1
    cudaStreamWaitEvent(s2, g_res.evG1, 0);
    k_agg<<<AGG_H1, 256, 0, s2>>>(s_xw1, b1, NH0, NH1, 0, nullptr, nullptr, nullptr);
    cudaEventRecord(g_res.evA1, s2);

    // default: agg1(h0) after setup, then gemm2(h0) [concurrent with agg1(h1)]
    cudaStreamWaitEvent(0, g_res.evB, 0);
    k_agg<<<AGG_H0, 256>>>(s_xw1, b1, 0, NH0, 0, nullptr, nullptr, nullptr);
    k_gemm<<<GEMM_H0, 512, SM_TOT>>>(nullptr, 1, 1, s_xw2, 0, NN);
    cudaStreamWaitEvent(0, g_res.evA1, 0);
    k_gemm<<<GEMM_H1, 512, SM_TOT>>>(nullptr, 1, 1, s_xw2, NH0, NN);
    cudaEventRecord(g_res.evG2, 0);               // all of gemm2 done

    // ---- layer 2 agg / layer 3 gemm, pipelined ----
    cudaStreamWaitEvent(s2, g_res.evG2, 0);
    k_agg<<<AGG_H1, 256, 0, s2>>>(s_xw2, b2, NH0, NH1, 0, nullptr, nullptr, nullptr);
    cudaEventRecord(g_res.evA2, s2);

    k_agg<<<AGG_H0, 256>>>(s_xw2, b2, 0, NH0, 0, nullptr, nullptr, nullptr);
    k_gemm<<<GEMM_H0, 512, SM_TOT>>>(nullptr, 1, 2, s_xw1, 0, NN);
    cudaStreamWaitEvent(0, g_res.evA2, 0);
    k_gemm<<<GEMM_H1, 512, SM_TOT>>>(nullptr, 1, 2, s_xw1, NH0, NN);

    // ---- layer 3 agg (full, fused final linear) ----
    k_agg<<<AGG_FULL, 256>>>(s_xw1, b3, 0, NN, 1, lw, lb, y);
}

// round 12
// speedup vs baseline: 1.2637x; 1.2637x over previous
#include <cuda_runtime.h>
#include <cuda_bf16.h>
#include <cuda_fp16.h>
#include <cstdint>

#define NN     100000
#define NEDGE  1600000
#define HID    128
#define SCAN_B 1024
#define NB1    ((NN + SCAN_B - 1) / SCAN_B)   // 98

// ---------------- scratch (static device globals; no allocation) ----------------
__device__ float  g_dinv[NN];
__device__ int    g_eidx[2 * NEDGE];
__device__ int    g_cnt[NN];
__device__ int    g_cur[NN];
__device__ int    g_rowptr[NN + 1];
__device__ int    g_bsum[NB1];
__device__ float2 g_csr[NEDGE];                 // {src (bitcast int), norm}
__device__ float  g_xw [(size_t)NN * HID];      // h @ W (fp32)
__device__ __half g_h  [(size_t)NN * HID];      // post-relu features (fp16, GEMM A input)
__device__ unsigned char g_wimg[3 * 32768];     // per-layer W fp16 plain [n][k] images
__device__ int    g_is64;

// ---------------- host-side stream/event resources ----------------
struct HxRes {
    cudaStream_t s2;
    cudaEvent_t evA, evB;
    HxRes() {
        cudaStreamCreateWithFlags(&s2, cudaStreamNonBlocking);
        cudaEventCreateWithFlags(&evA, cudaEventDisableTiming);
        cudaEventCreateWithFlags(&evB, cudaEventDisableTiming);
    }
};
static HxRes g_res;

// ================= helpers =================
__device__ __forceinline__ uint32_t smem_u32(const void* p) {
    uint32_t a;
    asm("{ .reg .u64 t; cvta.to.shared.u64 t, %1; cvt.u32.u64 %0, t; }" : "=r"(a) : "l"(p));
    return a;
}
__device__ __forceinline__ void ldsm_x4(uint32_t addr, uint32_t r[4]) {
    asm volatile("ldmatrix.sync.aligned.m8n8.x4.shared.b16 {%0,%1,%2,%3}, [%4];"
                 : "=r"(r[0]), "=r"(r[1]), "=r"(r[2]), "=r"(r[3]) : "r"(addr));
}
__device__ __forceinline__ void mma_f16(float c[4], const uint32_t a[4], const uint32_t* b) {
    asm volatile(
        "mma.sync.aligned.m16n8k16.row.col.f32.f16.f16.f32 "
        "{%0,%1,%2,%3}, {%4,%5,%6,%7}, {%8,%9}, {%0,%1,%2,%3};"
        : "+f"(c[0]), "+f"(c[1]), "+f"(c[2]), "+f"(c[3])
        : "r"(a[0]), "r"(a[1]), "r"(a[2]), "r"(a[3]), "r"(b[0]), "r"(b[1]));
}
__device__ __forceinline__ uint32_t h2pack(float lo, float hi) {
    __half2 h = __floats2half2_rn(lo, hi);
    return *(uint32_t*)&h;
}

// ---------------- edge index width detection ----------------
__global__ void k_detect(const int* __restrict__ w) {
    int zeros = 0;
    for (int i = 0; i < 256; i++) zeros += (w[2 * i + 1] == 0) ? 1 : 0;
    g_is64 = (zeros == 256) ? 1 : 0;
}

__global__ void k_zero() {
    int i = blockIdx.x * blockDim.x + threadIdx.x;
    if (i >= NN) return;
    g_dinv[i] = 1.0f;
    g_cnt[i] = 0;
    g_cur[i] = 0;
}

// ---------------- fused: convert + weighted degree + histogram ----------------
__global__ void k_prep(const void* __restrict__ p, const float* __restrict__ ew) {
    int e = blockIdx.x * blockDim.x + threadIdx.x;
    if (e >= NEDGE) return;
    int r, c;
    if (g_is64) {
        r = (int)((const long long*)p)[e];
        c = (int)((const long long*)p)[NEDGE + e];
    } else {
        r = ((const int*)p)[e];
        c = ((const int*)p)[NEDGE + e];
    }
    g_eidx[e] = r;
    g_eidx[NEDGE + e] = c;
    atomicAdd(&g_dinv[c], ew[e]);
    atomicAdd(&g_cnt[c], 1);
}

// ---------------- scan (block-level) + dinv finalize ----------------
__global__ __launch_bounds__(SCAN_B) void k_scan1() {
    __shared__ int sh[SCAN_B];
    int t = threadIdx.x;
    int i = blockIdx.x * SCAN_B + t;
    int v = (i < NN) ? g_cnt[i] : 0;
    sh[t] = v;
    if (i < NN) {
        float d = g_dinv[i];
        g_dinv[i] = (d > 0.0f) ? rsqrtf(d) : 0.0f;
    }
    __syncthreads();
#pragma unroll
    for (int off = 1; off < SCAN_B; off <<= 1) {
        int add = (t >= off) ? sh[t - off] : 0;
        __syncthreads();
        sh[t] += add;
        __syncthreads();
    }
    if (i < NN) g_rowptr[i] = sh[t] - v;
    if (t == SCAN_B - 1) g_bsum[blockIdx.x] = sh[t];
}

__global__ void k_scan2() {
    if (threadIdx.x == 0) {
        int run = 0;
        for (int b = 0; b < NB1; b++) { int s = g_bsum[b]; g_bsum[b] = run; run += s; }
    }
}

__global__ __launch_bounds__(SCAN_B) void k_scan3() {
    int i = blockIdx.x * SCAN_B + threadIdx.x;
    if (i < NN) g_rowptr[i] += g_bsum[blockIdx.x];
    if (i == 0) g_rowptr[NN] = NEDGE;
}

__global__ void k_scatter(const float* __restrict__ ew) {
    int e = blockIdx.x * blockDim.x + threadIdx.x;
    if (e >= NEDGE) return;
    int r = g_eidx[e];
    int c = g_eidx[NEDGE + e];
    float nm = g_dinv[r] * ew[e] * g_dinv[c];
    int pos = g_rowptr[c] + atomicAdd(&g_cur[c], 1);
    g_csr[pos] = make_float2(__int_as_float(r), nm);
}

// ---------------- W -> fp16 plain [n][k] image (B^T for row.col mma) ----------------
__global__ void k_wconv(const float* __restrict__ W, int layer) {
    int i = blockIdx.x * blockDim.x + threadIdx.x;
    if (i >= HID * HID) return;
    int n = i >> 7, k = i & 127;
    float w = W[k * HID + n];                       // B[n][k] = W[k][n]
    __half h = __float2half(w);
    *(uint16_t*)(g_wimg + (size_t)layer * 32768 + (size_t)(n * HID + k) * 2) =
        *(uint16_t*)&h;
}

// ---------------- mma.sync fp16 GEMM: [N,128] @ [128,128] -> g_xw ----------------
// CTA tile: M=256, 512 threads, 16 warps. Warp tile 64x32. Single fp16 pass.
// smem: A 256x272 (69632), B 128x272 (34816) = 104448 B.
#define TSTRIDE 272
#define SM_A    0
#define SM_B    69632
#define SM_TOT  104448

__global__ __launch_bounds__(512, 1) void k_gemm(const float* __restrict__ Ain,
                                                 int use_h, int layer, int n) {
    extern __shared__ char smem[];
    uint32_t sbase = smem_u32(smem);
    int tid = threadIdx.x;
    int wid = tid >> 5, lane = tid & 31;
    int rowBase = blockIdx.x * 256;
    int m_base = (wid & 3) * 64;
    int n_base = (wid >> 2) * 32;

    // --- A tile: 256 rows x 128 cols -> fp16 padded ---
    if (use_h) {
        // g_h is already fp16: raw copy with padding (4096 uint4 slots)
#pragma unroll
        for (int it = 0; it < 8; it++) {
            int item = tid + 512 * it;          // 0..4095
            int row = item >> 4, c8 = (item & 15) * 8;
            int grow = rowBase + row;
            uint4 v = make_uint4(0, 0, 0, 0);
            if (grow < n)
                v = *(const uint4*)(g_h + (size_t)grow * HID + c8);
            *(uint4*)(smem + SM_A + (uint32_t)row * TSTRIDE + c8 * 2) = v;
        }
    } else {
#pragma unroll
        for (int it = 0; it < 8; it++) {
            int item = tid + 512 * it;
            int row = item >> 4, c8 = (item & 15) * 8;
            int grow = rowBase + row;
            float f[8];
            if (grow < n) {
                float4 v0 = *(const float4*)(Ain + (size_t)grow * HID + c8);
                float4 v1 = *(const float4*)(Ain + (size_t)grow * HID + c8 + 4);
                f[0] = v0.x; f[1] = v0.y; f[2] = v0.z; f[3] = v0.w;
                f[4] = v1.x; f[5] = v1.y; f[6] = v1.z; f[7] = v1.w;
            } else {
#pragma unroll
                for (int j = 0; j < 8; j++) f[j] = 0.0f;
            }
            uint4 H = make_uint4(h2pack(f[0], f[1]), h2pack(f[2], f[3]),
                                 h2pack(f[4], f[5]), h2pack(f[6], f[7]));
            *(uint4*)(smem + SM_A + (uint32_t)row * TSTRIDE + c8 * 2) = H;
        }
    }

    // --- B tile: copy fp16 image into padded layout (2048 uint4 slots) ---
    {
        const uint4* src = (const uint4*)(g_wimg + (size_t)layer * 32768);
#pragma unroll
        for (int it = 0; it < 4; it++) {
            int item = tid + 512 * it;          // 0..2047
            int row = item >> 4, c8 = (item & 15) * 8;
            *(uint4*)(smem + SM_B + (uint32_t)row * TSTRIDE + c8 * 2) = src[item];
        }
    }
    __syncthreads();

    float acc[4][4][4];
#pragma unroll
    for (int mt = 0; mt < 4; mt++)
#pragma unroll
        for (int nt = 0; nt < 4; nt++)
#pragma unroll
            for (int c = 0; c < 4; c++) acc[mt][nt][c] = 0.0f;

    int aRow = lane & 15;
    int aCol = (lane >> 4) * 8;
    int bRow = (lane & 7) + ((lane >> 4) << 3);
    int bCol = ((lane >> 3) & 1) * 8;

    // --- single fp16 pass: 6 ldsm + 16 MMA per k-step ---
#pragma unroll
    for (int kk = 0; kk < 128; kk += 16) {
        uint32_t b[2][4];
#pragma unroll
        for (int np = 0; np < 2; np++) {
            uint32_t addr = sbase + SM_B + (uint32_t)(n_base + np * 16 + bRow) * TSTRIDE
                          + (kk + bCol) * 2;
            ldsm_x4(addr, b[np]);
        }
        uint32_t a[4][4];
#pragma unroll
        for (int mt = 0; mt < 4; mt++) {
            uint32_t ra = (uint32_t)(m_base + mt * 16 + aRow) * TSTRIDE + (kk + aCol) * 2;
            ldsm_x4(sbase + SM_A + ra, a[mt]);
        }
#pragma unroll
        for (int mt = 0; mt < 4; mt++)
#pragma unroll
            for (int nt = 0; nt < 4; nt++)
                mma_f16(acc[mt][nt], a[mt], &b[nt >> 1][(nt & 1) * 2]);
    }

    // --- epilogue: fp32 stores ---
#pragma unroll
    for (int mt = 0; mt < 4; mt++) {
        int r0 = rowBase + m_base + mt * 16 + (lane >> 2);
        int r1 = r0 + 8;
#pragma unroll
        for (int nt = 0; nt < 4; nt++) {
            int c0 = n_base + nt * 8 + (lane & 3) * 2;
            if (r0 < n)
                *(float2*)(g_xw + (size_t)r0 * HID + c0) =
                    make_float2(acc[mt][nt][0], acc[mt][nt][1]);
            if (r1 < n)
                *(float2*)(g_xw + (size_t)r1 * HID + c0) =
                    make_float2(acc[mt][nt][2], acc[mt][nt][3]);
        }
    }
}

// ---------------- pull aggregation: one warp per node, fp32 gathers ----------------
__global__ __launch_bounds__(256) void k_agg(const float* __restrict__ b,
                                             int last,
                                             const float* __restrict__ lw,
                                             const float* __restrict__ lb,
                                             float* __restrict__ y) {
    int gt = blockIdx.x * 256 + threadIdx.x;
    int node = gt >> 5;
    int lane = gt & 31;
    if (node >= NN) return;

    int s = g_rowptr[node];
    int e = g_rowptr[node + 1];

    float4 acc = make_float4(0.f, 0.f, 0.f, 0.f);
    int i = s;
    for (; i + 3 < e; i += 4) {
        float2 c0 = g_csr[i];
        float2 c1 = g_csr[i + 1];
        float2 c2 = g_csr[i + 2];
        float2 c3 = g_csr[i + 3];
        float4 v0 = *(const float4*)(g_xw + (size_t)__float_as_int(c0.x) * HID + lane * 4);
        float4 v1 = *(const float4*)(g_xw + (size_t)__float_as_int(c1.x) * HID + lane * 4);
        float4 v2 = *(const float4*)(g_xw + (size_t)__float_as_int(c2.x) * HID + lane * 4);
        float4 v3 = *(const float4*)(g_xw + (size_t)__float_as_int(c3.x) * HID + lane * 4);
        acc.x += c0.y * v0.x + c1.y * v1.x + c2.y * v2.x + c3.y * v3.x;
        acc.y += c0.y * v0.y + c1.y * v1.y + c2.y * v2.y + c3.y * v3.y;
        acc.z += c0.y * v0.z + c1.y * v1.z + c2.y * v2.z + c3.y * v3.z;
        acc.w += c0.y * v0.w + c1.y * v1.w + c2.y * v2.w + c3.y * v3.w;
    }
    for (; i < e; i++) {
        float2 c0 = g_csr[i];
        float4 v0 = *(const float4*)(g_xw + (size_t)__float_as_int(c0.x) * HID + lane * 4);
        acc.x += c0.y * v0.x;
        acc.y += c0.y * v0.y;
        acc.z += c0.y * v0.z;
        acc.w += c0.y * v0.w;
    }

    // self loop
    float di = g_dinv[node];
    float d2 = di * di;
    float4 sv = *(const float4*)(g_xw + (size_t)node * HID + lane * 4);
    acc.x += d2 * sv.x;
    acc.y += d2 * sv.y;
    acc.z += d2 * sv.z;
    acc.w += d2 * sv.w;

    float4 bb = *(const float4*)(b + lane * 4);
    float4 h;
    h.x = fmaxf(acc.x + bb.x, 0.f);
    h.y = fmaxf(acc.y + bb.y, 0.f);
    h.z = fmaxf(acc.z + bb.z, 0.f);
    h.w = fmaxf(acc.w + bb.w, 0.f);

    if (!last) {
        // store h as fp16 (GEMM A input)
        uint2 hp;
        hp.x = h2pack(h.x, h.y);
        hp.y = h2pack(h.z, h.w);
        *(uint2*)(g_h + (size_t)node * HID + lane * 4) = hp;
    } else {
        float4 w = *(const float4*)(lw + lane * 4);
        float sum = h.x * w.x + h.y * w.y + h.z * w.z + h.w * w.w;
#pragma unroll
        for (int off = 16; off > 0; off >>= 1)
            sum += __shfl_xor_sync(0xFFFFFFFFu, sum, off);
        if (lane == 0) y[node] = sum + lb[0];
    }
}

// ---------------- launch ----------------
extern "C" void kernel_launch(void* const* d_in, const int* in_sizes, int n_in,
                              void* d_out, int out_size) {
    const float* x   = (const float*)d_in[0];
    const void*  ei  = d_in[1];
    const float* ea  = (const float*)d_in[2];
    const float* W1  = (const float*)d_in[3];
    const float* b1  = (const float*)d_in[4];
    const float* W2  = (const float*)d_in[5];
    const float* b2  = (const float*)d_in[6];
    const float* W3  = (const float*)d_in[7];
    const float* b3  = (const float*)d_in[8];
    const float* lw  = (const float*)d_in[9];
    const float* lb  = (const float*)d_in[10];
    float* y = (float*)d_out;

    (void)in_sizes; (void)n_in; (void)out_size;

    static int s_attr_done = 0;
    if (!s_attr_done) {
        cudaFuncSetAttribute(k_gemm, cudaFuncAttributeMaxDynamicSharedMemorySize, SM_TOT);
        s_attr_done = 1;
    }

    const int GEMM_BLOCKS = (NN + 255) / 256;   // 391
    const int EW_BLOCKS   = (NEDGE + 255) / 256;
    const int NODE_BLOCKS = (NN + 255) / 256;
    const int AGG_BLOCKS  = (NN * 32) / 256;

    cudaStream_t s2 = g_res.s2;

    // fork: s2 branches off the capture (default) stream
    cudaEventRecord(g_res.evA, 0);
    cudaStreamWaitEvent(s2, g_res.evA, 0);

    // default stream: W images + layer-1 GEMM (k_gemm = 4th launch -> profiled)
    k_wconv<<<64, 256>>>(W1, 0);
    k_wconv<<<64, 256>>>(W2, 1);
    k_wconv<<<64, 256>>>(W3, 2);
    k_gemm<<<GEMM_BLOCKS, 512, SM_TOT>>>(x, 0, 0, NN);

    // s2: edge setup chain, concurrent with gemm1
    k_detect<<<1, 1, 0, s2>>>((const int*)ei);
    k_zero<<<NODE_BLOCKS, 256, 0, s2>>>();
    k_prep<<<EW_BLOCKS, 256, 0, s2>>>(ei, ea);
    k_scan1<<<NB1, SCAN_B, 0, s2>>>();
    k_scan2<<<1, 32, 0, s2>>>();
    k_scan3<<<NB1, SCAN_B, 0, s2>>>();
    k_scatter<<<EW_BLOCKS, 256, 0, s2>>>(ea);

    // join
    cudaEventRecord(g_res.evB, s2);
    cudaStreamWaitEvent(0, g_res.evB, 0);

    // serial layer chain (R7 skeleton)
    k_agg<<<AGG_BLOCKS, 256>>>(b1, 0, nullptr, nullptr, nullptr);
    k_gemm<<<GEMM_BLOCKS, 512, SM_TOT>>>(nullptr, 1, 1, NN);
    k_agg<<<AGG_BLOCKS, 256>>>(b2, 0, nullptr, nullptr, nullptr);
    k_gemm<<<GEMM_BLOCKS, 512, SM_TOT>>>(nullptr, 1, 2, NN);
    k_agg<<<AGG_BLOCKS, 256>>>(b3, 1, lw, lb, y);
}

// round 15
// speedup vs baseline: 1.5109x; 1.1956x over previous
#include <cuda_runtime.h>
#include <cuda_bf16.h>
#include <cuda_fp16.h>
#include <cstdint>

#define NN     100000
#define NEDGE  1600000
#define HID    128
#define SCAN_B 1024
#define NB1    ((NN + SCAN_B - 1) / SCAN_B)   // 98

// ---------------- scratch (static device globals; no allocation) ----------------
__device__ float  g_dinv[NN];
__device__ int    g_eidx[2 * NEDGE];
__device__ int    g_cnt[NN];
__device__ int    g_cur[NN];
__device__ int    g_rowptr[NN + 1];
__device__ int    g_bsum[NB1];
__device__ float2 g_csr[NEDGE];                 // {src (bitcast int), norm}
__device__ __half g_xw [(size_t)NN * HID];      // h @ W (fp16 end-to-end)
__device__ __half g_h  [(size_t)NN * HID];      // post-relu features (fp16, GEMM A input)
__device__ unsigned char g_wimg[3 * 32768];     // per-layer W fp16 plain [n][k] images
__device__ int    g_is64;

// ---------------- host-side stream/event resources ----------------
struct HxRes {
    cudaStream_t s2;
    cudaEvent_t evA, evB;
    HxRes() {
        cudaStreamCreateWithFlags(&s2, cudaStreamNonBlocking);
        cudaEventCreateWithFlags(&evA, cudaEventDisableTiming);
        cudaEventCreateWithFlags(&evB, cudaEventDisableTiming);
    }
};
static HxRes g_res;

// ================= helpers =================
__device__ __forceinline__ uint32_t smem_u32(const void* p) {
    uint32_t a;
    asm("{ .reg .u64 t; cvta.to.shared.u64 t, %1; cvt.u32.u64 %0, t; }" : "=r"(a) : "l"(p));
    return a;
}
__device__ __forceinline__ void ldsm_x4(uint32_t addr, uint32_t r[4]) {
    asm volatile("ldmatrix.sync.aligned.m8n8.x4.shared.b16 {%0,%1,%2,%3}, [%4];"
                 : "=r"(r[0]), "=r"(r[1]), "=r"(r[2]), "=r"(r[3]) : "r"(addr));
}
__device__ __forceinline__ void mma_f16(float c[4], const uint32_t a[4], const uint32_t* b) {
    asm volatile(
        "mma.sync.aligned.m16n8k16.row.col.f32.f16.f16.f32 "
        "{%0,%1,%2,%3}, {%4,%5,%6,%7}, {%8,%9}, {%0,%1,%2,%3};"
        : "+f"(c[0]), "+f"(c[1]), "+f"(c[2]), "+f"(c[3])
        : "r"(a[0]), "r"(a[1]), "r"(a[2]), "r"(a[3]), "r"(b[0]), "r"(b[1]));
}
__device__ __forceinline__ uint32_t h2pack(float lo, float hi) {
    __half2 h = __floats2half2_rn(lo, hi);
    return *(uint32_t*)&h;
}

// ---------------- edge index width detection ----------------
__global__ void k_detect(const int* __restrict__ w) {
    int zeros = 0;
    for (int i = 0; i < 256; i++) zeros += (w[2 * i + 1] == 0) ? 1 : 0;
    g_is64 = (zeros == 256) ? 1 : 0;
}

__global__ void k_zero() {
    int i = blockIdx.x * blockDim.x + threadIdx.x;
    if (i >= NN) return;
    g_dinv[i] = 1.0f;
    g_cnt[i] = 0;
    g_cur[i] = 0;
}

// ---------------- fused: convert + weighted degree + histogram ----------------
__global__ void k_prep(const void* __restrict__ p, const float* __restrict__ ew) {
    int e = blockIdx.x * blockDim.x + threadIdx.x;
    if (e >= NEDGE) return;
    int r, c;
    if (g_is64) {
        r = (int)((const long long*)p)[e];
        c = (int)((const long long*)p)[NEDGE + e];
    } else {
        r = ((const int*)p)[e];
        c = ((const int*)p)[NEDGE + e];
    }
    g_eidx[e] = r;
    g_eidx[NEDGE + e] = c;
    atomicAdd(&g_dinv[c], ew[e]);
    atomicAdd(&g_cnt[c], 1);
}

// ---------------- scan (block-level) + dinv finalize ----------------
__global__ __launch_bounds__(SCAN_B) void k_scan1() {
    __shared__ int sh[SCAN_B];
    int t = threadIdx.x;
    int i = blockIdx.x * SCAN_B + t;
    int v = (i < NN) ? g_cnt[i] : 0;
    sh[t] = v;
    if (i < NN) {
        float d = g_dinv[i];
        g_dinv[i] = (d > 0.0f) ? rsqrtf(d) : 0.0f;
    }
    __syncthreads();
#pragma unroll
    for (int off = 1; off < SCAN_B; off <<= 1) {
        int add = (t >= off) ? sh[t - off] : 0;
        __syncthreads();
        sh[t] += add;
        __syncthreads();
    }
    if (i < NN) g_rowptr[i] = sh[t] - v;
    if (t == SCAN_B - 1) g_bsum[blockIdx.x] = sh[t];
}

__global__ void k_scan2() {
    if (threadIdx.x == 0) {
        int run = 0;
        for (int b = 0; b < NB1; b++) { int s = g_bsum[b]; g_bsum[b] = run; run += s; }
    }
}

__global__ __launch_bounds__(SCAN_B) void k_scan3() {
    int i = blockIdx.x * SCAN_B + threadIdx.x;
    if (i < NN) g_rowptr[i] += g_bsum[blockIdx.x];
    if (i == 0) g_rowptr[NN] = NEDGE;
}

__global__ void k_scatter(const float* __restrict__ ew) {
    int e = blockIdx.x * blockDim.x + threadIdx.x;
    if (e >= NEDGE) return;
    int r = g_eidx[e];
    int c = g_eidx[NEDGE + e];
    float nm = g_dinv[r] * ew[e] * g_dinv[c];
    int pos = g_rowptr[c] + atomicAdd(&g_cur[c], 1);
    g_csr[pos] = make_float2(__int_as_float(r), nm);
}

// ---------------- W -> fp16 plain [n][k] image (B^T for row.col mma) ----------------
__global__ void k_wconv(const float* __restrict__ W, int layer) {
    int i = blockIdx.x * blockDim.x + threadIdx.x;
    if (i >= HID * HID) return;
    int n = i >> 7, k = i & 127;
    float w = W[k * HID + n];                       // B[n][k] = W[k][n]
    __half h = __float2half(w);
    *(uint16_t*)(g_wimg + (size_t)layer * 32768 + (size_t)(n * HID + k) * 2) =
        *(uint16_t*)&h;
}

// ---------------- mma.sync fp16 GEMM: [N,128] @ [128,128] -> g_xw (fp16) ----------------
// CTA tile: M=256, 512 threads, 16 warps. Warp tile 64x32. Single fp16 pass.
#define TSTRIDE 272
#define SM_A    0
#define SM_B    69632
#define SM_TOT  104448

__global__ __launch_bounds__(512, 1) void k_gemm(const float* __restrict__ Ain,
                                                 int use_h, int layer, int n) {
    extern __shared__ char smem[];
    uint32_t sbase = smem_u32(smem);
    int tid = threadIdx.x;
    int wid = tid >> 5, lane = tid & 31;
    int rowBase = blockIdx.x * 256;
    int m_base = (wid & 3) * 64;
    int n_base = (wid >> 2) * 32;

    // --- A tile: 256 rows x 128 cols -> fp16 padded ---
    if (use_h) {
#pragma unroll
        for (int it = 0; it < 8; it++) {
            int item = tid + 512 * it;          // 0..4095
            int row = item >> 4, c8 = (item & 15) * 8;
            int grow = rowBase + row;
            uint4 v = make_uint4(0, 0, 0, 0);
            if (grow < n)
                v = *(const uint4*)(g_h + (size_t)grow * HID + c8);
            *(uint4*)(smem + SM_A + (uint32_t)row * TSTRIDE + c8 * 2) = v;
        }
    } else {
#pragma unroll
        for (int it = 0; it < 8; it++) {
            int item = tid + 512 * it;
            int row = item >> 4, c8 = (item & 15) * 8;
            int grow = rowBase + row;
            float f[8];
            if (grow < n) {
                float4 v0 = *(const float4*)(Ain + (size_t)grow * HID + c8);
                float4 v1 = *(const float4*)(Ain + (size_t)grow * HID + c8 + 4);
                f[0] = v0.x; f[1] = v0.y; f[2] = v0.z; f[3] = v0.w;
                f[4] = v1.x; f[5] = v1.y; f[6] = v1.z; f[7] = v1.w;
            } else {
#pragma unroll
                for (int j = 0; j < 8; j++) f[j] = 0.0f;
            }
            uint4 H = make_uint4(h2pack(f[0], f[1]), h2pack(f[2], f[3]),
                                 h2pack(f[4], f[5]), h2pack(f[6], f[7]));
            *(uint4*)(smem + SM_A + (uint32_t)row * TSTRIDE + c8 * 2) = H;
        }
    }

    // --- B tile: copy fp16 image into padded layout ---
    {
        const uint4* src = (const uint4*)(g_wimg + (size_t)layer * 32768);
#pragma unroll
        for (int it = 0; it < 4; it++) {
            int item = tid + 512 * it;          // 0..2047
            int row = item >> 4, c8 = (item & 15) * 8;
            *(uint4*)(smem + SM_B + (uint32_t)row * TSTRIDE + c8 * 2) = src[item];
        }
    }
    __syncthreads();

    float acc[4][4][4];
#pragma unroll
    for (int mt = 0; mt < 4; mt++)
#pragma unroll
        for (int nt = 0; nt < 4; nt++)
#pragma unroll
            for (int c = 0; c < 4; c++) acc[mt][nt][c] = 0.0f;

    int aRow = lane & 15;
    int aCol = (lane >> 4) * 8;
    int bRow = (lane & 7) + ((lane >> 4) << 3);
    int bCol = ((lane >> 3) & 1) * 8;

#pragma unroll
    for (int kk = 0; kk < 128; kk += 16) {
        uint32_t b[2][4];
#pragma unroll
        for (int np = 0; np < 2; np++) {
            uint32_t addr = sbase + SM_B + (uint32_t)(n_base + np * 16 + bRow) * TSTRIDE
                          + (kk + bCol) * 2;
            ldsm_x4(addr, b[np]);
        }
        uint32_t a[4][4];
#pragma unroll
        for (int mt = 0; mt < 4; mt++) {
            uint32_t ra = (uint32_t)(m_base + mt * 16 + aRow) * TSTRIDE + (kk + aCol) * 2;
            ldsm_x4(sbase + SM_A + ra, a[mt]);
        }
#pragma unroll
        for (int mt = 0; mt < 4; mt++)
#pragma unroll
            for (int nt = 0; nt < 4; nt++)
                mma_f16(acc[mt][nt], a[mt], &b[nt >> 1][(nt & 1) * 2]);
    }

    // --- epilogue: fp16 stores (halved write traffic) ---
#pragma unroll
    for (int mt = 0; mt < 4; mt++) {
        int r0 = rowBase + m_base + mt * 16 + (lane >> 2);
        int r1 = r0 + 8;
#pragma unroll
        for (int nt = 0; nt < 4; nt++) {
            int c0 = n_base + nt * 8 + (lane & 3) * 2;
            if (r0 < n)
                *(uint32_t*)(g_xw + (size_t)r0 * HID + c0) =
                    h2pack(acc[mt][nt][0], acc[mt][nt][1]);
            if (r1 < n)
                *(uint32_t*)(g_xw + (size_t)r1 * HID + c0) =
                    h2pack(acc[mt][nt][2], acc[mt][nt][3]);
        }
    }
}

// ---------------- pull aggregation: one warp per node, fp16 gathers ----------------
__global__ __launch_bounds__(256) void k_agg(const float* __restrict__ b,
                                             int last,
                                             const float* __restrict__ lw,
                                             const float* __restrict__ lb,
                                             float* __restrict__ y) {
    int gt = blockIdx.x * 256 + threadIdx.x;
    int node = gt >> 5;
    int lane = gt & 31;
    if (node >= NN) return;

    int s = g_rowptr[node];
    int e = g_rowptr[node + 1];

    float4 acc = make_float4(0.f, 0.f, 0.f, 0.f);
    int i = s;
    // unroll 8 for MLP (each gather = 256B row slice, 2 lines)
    for (; i + 7 < e; i += 8) {
        float2 cc[8];
        uint2  mm[8];
#pragma unroll
        for (int j = 0; j < 8; j++) cc[j] = g_csr[i + j];
#pragma unroll
        for (int j = 0; j < 8; j++)
            mm[j] = *(const uint2*)(g_xw + (size_t)__float_as_int(cc[j].x) * HID + lane * 4);
#pragma unroll
        for (int j = 0; j < 8; j++) {
            float2 a0 = __half22float2(*(__half2*)&mm[j].x);
            float2 a1 = __half22float2(*(__half2*)&mm[j].y);
            acc.x += cc[j].y * a0.x;
            acc.y += cc[j].y * a0.y;
            acc.z += cc[j].y * a1.x;
            acc.w += cc[j].y * a1.y;
        }
    }
    for (; i < e; i++) {
        float2 c0 = g_csr[i];
        uint2 m0 = *(const uint2*)(g_xw + (size_t)__float_as_int(c0.x) * HID + lane * 4);
        float2 a0 = __half22float2(*(__half2*)&m0.x);
        float2 a1 = __half22float2(*(__half2*)&m0.y);
        acc.x += c0.y * a0.x;
        acc.y += c0.y * a0.y;
        acc.z += c0.y * a1.x;
        acc.w += c0.y * a1.y;
    }

    // self loop (fp16 read)
    float di = g_dinv[node];
    float d2 = di * di;
    uint2 ms = *(const uint2*)(g_xw + (size_t)node * HID + lane * 4);
    {
        float2 a0 = __half22float2(*(__half2*)&ms.x);
        float2 a1 = __half22float2(*(__half2*)&ms.y);
        acc.x += d2 * a0.x;
        acc.y += d2 * a0.y;
        acc.z += d2 * a1.x;
        acc.w += d2 * a1.y;
    }

    float4 bb = *(const float4*)(b + lane * 4);
    float4 h;
    h.x = fmaxf(acc.x + bb.x, 0.f);
    h.y = fmaxf(acc.y + bb.y, 0.f);
    h.z = fmaxf(acc.z + bb.z, 0.f);
    h.w = fmaxf(acc.w + bb.w, 0.f);

    if (!last) {
        uint2 hp;
        hp.x = h2pack(h.x, h.y);
        hp.y = h2pack(h.z, h.w);
        *(uint2*)(g_h + (size_t)node * HID + lane * 4) = hp;
    } else {
        float4 w = *(const float4*)(lw + lane * 4);
        float sum = h.x * w.x + h.y * w.y + h.z * w.z + h.w * w.w;
#pragma unroll
        for (int off = 16; off > 0; off >>= 1)
            sum += __shfl_xor_sync(0xFFFFFFFFu, sum, off);
        if (lane == 0) y[node] = sum + lb[0];
    }
}

// ---------------- launch ----------------
extern "C" void kernel_launch(void* const* d_in, const int* in_sizes, int n_in,
                              void* d_out, int out_size) {
    const float* x   = (const float*)d_in[0];
    const void*  ei  = d_in[1];
    const float* ea  = (const float*)d_in[2];
    const float* W1  = (const float*)d_in[3];
    const float* b1  = (const float*)d_in[4];
    const float* W2  = (const float*)d_in[5];
    const float* b2  = (const float*)d_in[6];
    const float* W3  = (const float*)d_in[7];
    const float* b3  = (const float*)d_in[8];
    const float* lw  = (const float*)d_in[9];
    const float* lb  = (const float*)d_in[10];
    float* y = (float*)d_out;

    (void)in_sizes; (void)n_in; (void)out_size;

    static int s_attr_done = 0;
    if (!s_attr_done) {
        cudaFuncSetAttribute(k_gemm, cudaFuncAttributeMaxDynamicSharedMemorySize, SM_TOT);
        s_attr_done = 1;
    }

    const int GEMM_BLOCKS = (NN + 255) / 256;   // 391
    const int EW_BLOCKS   = (NEDGE + 255) / 256;
    const int NODE_BLOCKS = (NN + 255) / 256;
    const int AGG_BLOCKS  = (NN * 32) / 256;

    cudaStream_t s2 = g_res.s2;

    // fork: s2 branches off the capture (default) stream
    cudaEventRecord(g_res.evA, 0);
    cudaStreamWaitEvent(s2, g_res.evA, 0);

    // default stream: W images + layer-1 GEMM (k_gemm = 4th launch -> profiled)
    k_wconv<<<64, 256>>>(W1, 0);
    k_wconv<<<64, 256>>>(W2, 1);
    k_wconv<<<64, 256>>>(W3, 2);
    k_gemm<<<GEMM_BLOCKS, 512, SM_TOT>>>(x, 0, 0, NN);

    // s2: edge setup chain, concurrent with gemm1
    k_detect<<<1, 1, 0, s2>>>((const int*)ei);
    k_zero<<<NODE_BLOCKS, 256, 0, s2>>>();
    k_prep<<<EW_BLOCKS, 256, 0, s2>>>(ei, ea);
    k_scan1<<<NB1, SCAN_B, 0, s2>>>();
    k_scan2<<<1, 32, 0, s2>>>();
    k_scan3<<<NB1, SCAN_B, 0, s2>>>();
    k_scatter<<<EW_BLOCKS, 256, 0, s2>>>(ea);

    // join
    cudaEventRecord(g_res.evB, s2);
    cudaStreamWaitEvent(0, g_res.evB, 0);

    // serial layer chain
    k_agg<<<AGG_BLOCKS, 256>>>(b1, 0, nullptr, nullptr, nullptr);
    k_gemm<<<GEMM_BLOCKS, 512, SM_TOT>>>(nullptr, 1, 1, NN);
    k_agg<<<AGG_BLOCKS, 256>>>(b2, 0, nullptr, nullptr, nullptr);
    k_gemm<<<GEMM_BLOCKS, 512, SM_TOT>>>(nullptr, 1, 2, NN);
    k_agg<<<AGG_BLOCKS, 256>>>(b3, 1, lw, lb, y);
}

// round 16
// speedup vs baseline: 1.5135x; 1.0018x over previous
#include <cuda_runtime.h>
#include <cuda_bf16.h>
#include <cuda_fp16.h>
#include <cstdint>

#define NN     100000
#define NEDGE  1600000
#define HID    128
#define SCAN_B 1024
#define NB1    ((NN + SCAN_B - 1) / SCAN_B)   // 98

// ---------------- scratch (static device globals; no allocation) ----------------
__device__ float  g_dinv[NN];
__device__ int    g_cnt[NN];
__device__ int    g_cur[NN];
__device__ int    g_rowptr[NN + 1];
__device__ int    g_bsum[NB1];
__device__ float2 g_csr[NEDGE];                 // {src (bitcast int), norm}
__device__ __half g_xw [(size_t)NN * HID];      // h @ W (fp16 end-to-end)
__device__ __half g_h  [(size_t)NN * HID];      // post-relu features (fp16, GEMM A input)
__device__ unsigned char g_wimg[3 * 32768];     // per-layer W fp16 plain [n][k] images
__device__ int    g_is64;

// ---------------- host-side stream/event resources ----------------
struct HxRes {
    cudaStream_t s2;
    cudaEvent_t evA, evB;
    HxRes() {
        cudaStreamCreateWithFlags(&s2, cudaStreamNonBlocking);
        cudaEventCreateWithFlags(&evA, cudaEventDisableTiming);
        cudaEventCreateWithFlags(&evB, cudaEventDisableTiming);
    }
};
static HxRes g_res;

// ================= helpers =================
__device__ __forceinline__ uint32_t smem_u32(const void* p) {
    uint32_t a;
    asm("{ .reg .u64 t; cvta.to.shared.u64 t, %1; cvt.u32.u64 %0, t; }" : "=r"(a) : "l"(p));
    return a;
}
__device__ __forceinline__ void ldsm_x4(uint32_t addr, uint32_t r[4]) {
    asm volatile("ldmatrix.sync.aligned.m8n8.x4.shared.b16 {%0,%1,%2,%3}, [%4];"
                 : "=r"(r[0]), "=r"(r[1]), "=r"(r[2]), "=r"(r[3]) : "r"(addr));
}
__device__ __forceinline__ void mma_f16(float c[4], const uint32_t a[4], const uint32_t* b) {
    asm volatile(
        "mma.sync.aligned.m16n8k16.row.col.f32.f16.f16.f32 "
        "{%0,%1,%2,%3}, {%4,%5,%6,%7}, {%8,%9}, {%0,%1,%2,%3};"
        : "+f"(c[0]), "+f"(c[1]), "+f"(c[2]), "+f"(c[3])
        : "r"(a[0]), "r"(a[1]), "r"(a[2]), "r"(a[3]), "r"(b[0]), "r"(b[1]));
}
__device__ __forceinline__ uint32_t h2pack(float lo, float hi) {
    __half2 h = __floats2half2_rn(lo, hi);
    return *(uint32_t*)&h;
}
__device__ __forceinline__ void edge_rc(const void* p, int e, int& r, int& c) {
    if (g_is64) {
        r = (int)((const long long*)p)[e];
        c = (int)((const long long*)p)[NEDGE + e];
    } else {
        r = ((const int*)p)[e];
        c = ((const int*)p)[NEDGE + e];
    }
}

// ---------------- edge index width detection ----------------
__global__ void k_detect(const int* __restrict__ w) {
    int zeros = 0;
    for (int i = 0; i < 256; i++) zeros += (w[2 * i + 1] == 0) ? 1 : 0;
    g_is64 = (zeros == 256) ? 1 : 0;
}

__global__ void k_zero() {
    int i = blockIdx.x * blockDim.x + threadIdx.x;
    if (i >= NN) return;
    g_dinv[i] = 1.0f;
    g_cnt[i] = 0;
    g_cur[i] = 0;
}

// ---------------- weighted degree + histogram (no index staging) ----------------
__global__ void k_prep(const void* __restrict__ p, const float* __restrict__ ew) {
    int e = blockIdx.x * blockDim.x + threadIdx.x;
    if (e >= NEDGE) return;
    int r, c;
    edge_rc(p, e, r, c);
    (void)r;
    atomicAdd(&g_dinv[c], ew[e]);
    atomicAdd(&g_cnt[c], 1);
}

// ---------------- scan (block-level) + dinv finalize ----------------
__global__ __launch_bounds__(SCAN_B) void k_scan1() {
    __shared__ int sh[SCAN_B];
    int t = threadIdx.x;
    int i = blockIdx.x * SCAN_B + t;
    int v = (i < NN) ? g_cnt[i] : 0;
    sh[t] = v;
    if (i < NN) {
        float d = g_dinv[i];
        g_dinv[i] = (d > 0.0f) ? rsqrtf(d) : 0.0f;
    }
    __syncthreads();
#pragma unroll
    for (int off = 1; off < SCAN_B; off <<= 1) {
        int add = (t >= off) ? sh[t - off] : 0;
        __syncthreads();
        sh[t] += add;
        __syncthreads();
    }
    if (i < NN) g_rowptr[i] = sh[t] - v;
    if (t == SCAN_B - 1) g_bsum[blockIdx.x] = sh[t];
}

__global__ void k_scan2() {
    if (threadIdx.x == 0) {
        int run = 0;
        for (int b = 0; b < NB1; b++) { int s = g_bsum[b]; g_bsum[b] = run; run += s; }
    }
}

__global__ __launch_bounds__(SCAN_B) void k_scan3() {
    int i = blockIdx.x * SCAN_B + threadIdx.x;
    if (i < NN) g_rowptr[i] += g_bsum[blockIdx.x];
    if (i == 0) g_rowptr[NN] = NEDGE;
}

// ---------------- scatter: reads edge index directly from input ----------------
__global__ void k_scatter(const void* __restrict__ p, const float* __restrict__ ew) {
    int e = blockIdx.x * blockDim.x + threadIdx.x;
    if (e >= NEDGE) return;
    int r, c;
    edge_rc(p, e, r, c);
    float nm = g_dinv[r] * ew[e] * g_dinv[c];
    int pos = g_rowptr[c] + atomicAdd(&g_cur[c], 1);
    g_csr[pos] = make_float2(__int_as_float(r), nm);
}

// ---------------- W -> fp16 plain [n][k] image (B^T for row.col mma) ----------------
__global__ void k_wconv(const float* __restrict__ W, int layer) {
    int i = blockIdx.x * blockDim.x + threadIdx.x;
    if (i >= HID * HID) return;
    int n = i >> 7, k = i & 127;
    float w = W[k * HID + n];                       // B[n][k] = W[k][n]
    __half h = __float2half(w);
    *(uint16_t*)(g_wimg + (size_t)layer * 32768 + (size_t)(n * HID + k) * 2) =
        *(uint16_t*)&h;
}

// ---------------- mma.sync fp16 GEMM: [N,128] @ [128,128] -> g_xw (fp16) ----------------
#define TSTRIDE 272
#define SM_A    0
#define SM_B    69632
#define SM_TOT  104448

__global__ __launch_bounds__(512, 1) void k_gemm(const float* __restrict__ Ain,
                                                 int use_h, int layer, int n) {
    extern __shared__ char smem[];
    uint32_t sbase = smem_u32(smem);
    int tid = threadIdx.x;
    int wid = tid >> 5, lane = tid & 31;
    int rowBase = blockIdx.x * 256;
    int m_base = (wid & 3) * 64;
    int n_base = (wid >> 2) * 32;

    // --- A tile: 256 rows x 128 cols -> fp16 padded ---
    if (use_h) {
#pragma unroll
        for (int it = 0; it < 8; it++) {
            int item = tid + 512 * it;          // 0..4095
            int row = item >> 4, c8 = (item & 15) * 8;
            int grow = rowBase + row;
            uint4 v = make_uint4(0, 0, 0, 0);
            if (grow < n)
                v = *(const uint4*)(g_h + (size_t)grow * HID + c8);
            *(uint4*)(smem + SM_A + (uint32_t)row * TSTRIDE + c8 * 2) = v;
        }
    } else {
#pragma unroll
        for (int it = 0; it < 8; it++) {
            int item = tid + 512 * it;
            int row = item >> 4, c8 = (item & 15) * 8;
            int grow = rowBase + row;
            float f[8];
            if (grow < n) {
                float4 v0 = *(const float4*)(Ain + (size_t)grow * HID + c8);
                float4 v1 = *(const float4*)(Ain + (size_t)grow * HID + c8 + 4);
                f[0] = v0.x; f[1] = v0.y; f[2] = v0.z; f[3] = v0.w;
                f[4] = v1.x; f[5] = v1.y; f[6] = v1.z; f[7] = v1.w;
            } else {
#pragma unroll
                for (int j = 0; j < 8; j++) f[j] = 0.0f;
            }
            uint4 H = make_uint4(h2pack(f[0], f[1]), h2pack(f[2], f[3]),
                                 h2pack(f[4], f[5]), h2pack(f[6], f[7]));
            *(uint4*)(smem + SM_A + (uint32_t)row * TSTRIDE + c8 * 2) = H;
        }
    }

    // --- B tile: copy fp16 image into padded layout ---
    {
        const uint4* src = (const uint4*)(g_wimg + (size_t)layer * 32768);
#pragma unroll
        for (int it = 0; it < 4; it++) {
            int item = tid + 512 * it;          // 0..2047
            int row = item >> 4, c8 = (item & 15) * 8;
            *(uint4*)(smem + SM_B + (uint32_t)row * TSTRIDE + c8 * 2) = src[item];
        }
    }
    __syncthreads();

    float acc[4][4][4];
#pragma unroll
    for (int mt = 0; mt < 4; mt++)
#pragma unroll
        for (int nt = 0; nt < 4; nt++)
#pragma unroll
            for (int c = 0; c < 4; c++) acc[mt][nt][c] = 0.0f;

    int aRow = lane & 15;
    int aCol = (lane >> 4) * 8;
    int bRow = (lane & 7) + ((lane >> 4) << 3);
    int bCol = ((lane >> 3) & 1) * 8;

#pragma unroll
    for (int kk = 0; kk < 128; kk += 16) {
        uint32_t b[2][4];
#pragma unroll
        for (int np = 0; np < 2; np++) {
            uint32_t addr = sbase + SM_B + (uint32_t)(n_base + np * 16 + bRow) * TSTRIDE
                          + (kk + bCol) * 2;
            ldsm_x4(addr, b[np]);
        }
        uint32_t a[4][4];
#pragma unroll
        for (int mt = 0; mt < 4; mt++) {
            uint32_t ra = (uint32_t)(m_base + mt * 16 + aRow) * TSTRIDE + (kk + aCol) * 2;
            ldsm_x4(sbase + SM_A + ra, a[mt]);
        }
#pragma unroll
        for (int mt = 0; mt < 4; mt++)
#pragma unroll
            for (int nt = 0; nt < 4; nt++)
                mma_f16(acc[mt][nt], a[mt], &b[nt >> 1][(nt & 1) * 2]);
    }

    // --- epilogue: fp16 stores ---
#pragma unroll
    for (int mt = 0; mt < 4; mt++) {
        int r0 = rowBase + m_base + mt * 16 + (lane >> 2);
        int r1 = r0 + 8;
#pragma unroll
        for (int nt = 0; nt < 4; nt++) {
            int c0 = n_base + nt * 8 + (lane & 3) * 2;
            if (r0 < n)
                *(uint32_t*)(g_xw + (size_t)r0 * HID + c0) =
                    h2pack(acc[mt][nt][0], acc[mt][nt][1]);
            if (r1 < n)
                *(uint32_t*)(g_xw + (size_t)r1 * HID + c0) =
                    h2pack(acc[mt][nt][2], acc[mt][nt][3]);
        }
    }
}

// ---------------- pull aggregation: one warp per node, fp16 gathers ----------------
__global__ __launch_bounds__(256) void k_agg(const float* __restrict__ b,
                                             int last,
                                             const float* __restrict__ lw,
                                             const float* __restrict__ lb,
                                             float* __restrict__ y) {
    int gt = blockIdx.x * 256 + threadIdx.x;
    int node = gt >> 5;
    int lane = gt & 31;
    if (node >= NN) return;

    int s = g_rowptr[node];
    int e = g_rowptr[node + 1];

    float4 acc = make_float4(0.f, 0.f, 0.f, 0.f);
    int i = s;
    for (; i + 7 < e; i += 8) {
        float2 cc[8];
        uint2  mm[8];
#pragma unroll
        for (int j = 0; j < 8; j++) cc[j] = g_csr[i + j];
#pragma unroll
        for (int j = 0; j < 8; j++)
            mm[j] = *(const uint2*)(g_xw + (size_t)__float_as_int(cc[j].x) * HID + lane * 4);
#pragma unroll
        for (int j = 0; j < 8; j++) {
            float2 a0 = __half22float2(*(__half2*)&mm[j].x);
            float2 a1 = __half22float2(*(__half2*)&mm[j].y);
            acc.x += cc[j].y * a0.x;
            acc.y += cc[j].y * a0.y;
            acc.z += cc[j].y * a1.x;
            acc.w += cc[j].y * a1.y;
        }
    }
    for (; i < e; i++) {
        float2 c0 = g_csr[i];
        uint2 m0 = *(const uint2*)(g_xw + (size_t)__float_as_int(c0.x) * HID + lane * 4);
        float2 a0 = __half22float2(*(__half2*)&m0.x);
        float2 a1 = __half22float2(*(__half2*)&m0.y);
        acc.x += c0.y * a0.x;
        acc.y += c0.y * a0.y;
        acc.z += c0.y * a1.x;
        acc.w += c0.y * a1.y;
    }

    // self loop (fp16 read)
    float di = g_dinv[node];
    float d2 = di * di;
    uint2 ms = *(const uint2*)(g_xw + (size_t)node * HID + lane * 4);
    {
        float2 a0 = __half22float2(*(__half2*)&ms.x);
        float2 a1 = __half22float2(*(__half2*)&ms.y);
        acc.x += d2 * a0.x;
        acc.y += d2 * a0.y;
        acc.z += d2 * a1.x;
        acc.w += d2 * a1.y;
    }

    float4 bb = *(const float4*)(b + lane * 4);
    float4 h;
    h.x = fmaxf(acc.x + bb.x, 0.f);
    h.y = fmaxf(acc.y + bb.y, 0.f);
    h.z = fmaxf(acc.z + bb.z, 0.f);
    h.w = fmaxf(acc.w + bb.w, 0.f);

    if (!last) {
        uint2 hp;
        hp.x = h2pack(h.x, h.y);
        hp.y = h2pack(h.z, h.w);
        *(uint2*)(g_h + (size_t)node * HID + lane * 4) = hp;
    } else {
        float4 w = *(const float4*)(lw + lane * 4);
        float sum = h.x * w.x + h.y * w.y + h.z * w.z + h.w * w.w;
#pragma unroll
        for (int off = 16; off > 0; off >>= 1)
            sum += __shfl_xor_sync(0xFFFFFFFFu, sum, off);
        if (lane == 0) y[node] = sum + lb[0];
    }
}

// ---------------- launch ----------------
extern "C" void kernel_launch(void* const* d_in, const int* in_sizes, int n_in,
                              void* d_out, int out_size) {
    const float* x   = (const float*)d_in[0];
    const void*  ei  = d_in[1];
    const float* ea  = (const float*)d_in[2];
    const float* W1  = (const float*)d_in[3];
    const float* b1  = (const float*)d_in[4];
    const float* W2  = (const float*)d_in[5];
    const float* b2  = (const float*)d_in[6];
    const float* W3  = (const float*)d_in[7];
    const float* b3  = (const float*)d_in[8];
    const float* lw  = (const float*)d_in[9];
    const float* lb  = (const float*)d_in[10];
    float* y = (float*)d_out;

    (void)in_sizes; (void)n_in; (void)out_size;

    static int s_attr_done = 0;
    if (!s_attr_done) {
        cudaFuncSetAttribute(k_gemm, cudaFuncAttributeMaxDynamicSharedMemorySize, SM_TOT);
        s_attr_done = 1;
    }

    const int GEMM_BLOCKS = (NN + 255) / 256;   // 391
    const int EW_BLOCKS   = (NEDGE + 255) / 256;
    const int NODE_BLOCKS = (NN + 255) / 256;
    const int AGG_BLOCKS  = (NN * 32) / 256;

    cudaStream_t s2 = g_res.s2;

    // fork: s2 branches off the capture (default) stream
    cudaEventRecord(g_res.evA, 0);
    cudaStreamWaitEvent(s2, g_res.evA, 0);

    // submission order chosen so k_prep is the 4th launch (profiled this round)
    k_detect<<<1, 1, 0, s2>>>((const int*)ei);      // 1 (s2)
    k_zero<<<NODE_BLOCKS, 256, 0, s2>>>();          // 2 (s2)
    k_wconv<<<64, 256>>>(W1, 0);                    // 3 (default)
    k_prep<<<EW_BLOCKS, 256, 0, s2>>>(ei, ea);      // 4 (s2)  <- profiled
    k_scan1<<<NB1, SCAN_B, 0, s2>>>();              // 5
    k_scan2<<<1, 32, 0, s2>>>();                    // 6
    k_scan3<<<NB1, SCAN_B, 0, s2>>>();              // 7
    k_scatter<<<EW_BLOCKS, 256, 0, s2>>>(ei, ea);   // 8

    // default: gemm1 (needs wconv1 only), then remaining W images
    k_gemm<<<GEMM_BLOCKS, 512, SM_TOT>>>(x, 0, 0, NN);  // 9
    k_wconv<<<64, 256>>>(W2, 1);                        // 10
    k_wconv<<<64, 256>>>(W3, 2);                        // 11

    // join
    cudaEventRecord(g_res.evB, s2);
    cudaStreamWaitEvent(0, g_res.evB, 0);

    // serial layer chain
    k_agg<<<AGG_BLOCKS, 256>>>(b1, 0, nullptr, nullptr, nullptr);
    k_gemm<<<GEMM_BLOCKS, 512, SM_TOT>>>(nullptr, 1, 1, NN);
    k_agg<<<AGG_BLOCKS, 256>>>(b2, 0, nullptr, nullptr, nullptr);
    k_gemm<<<GEMM_BLOCKS, 512, SM_TOT>>>(nullptr, 1, 2, NN);
    k_agg<<<AGG_BLOCKS, 256>>>(b3, 1, lw, lb, y);
}